// round 2
// baseline (speedup 1.0000x reference)
#include <cuda_runtime.h>
#include <cuda_bf16.h>
#include <math.h>

// ---------------------------------------------------------------------------
// Problem constants
// ---------------------------------------------------------------------------
#define T_HORIZON 65536
#define S_DIM     128
#define A_DIM     8
#define HID       256
#define GAMMA     0.99f
#define LMBDA     0.95f
#define EPS_CLIP  0.2f
#define VF_COEF   0.5f
#define ENT_COEF  0.01f
#define LOG2PI_F  1.8378770664093453f

// Tile config for the fused MLP kernel
#define TM   128          // rows per block
#define KT   16           // K slice
#define XPAD 132          // 128 + 4 pad (bank-conflict avoidance)
#define HPAD 264          // 256 + 8 pad

// ---------------------------------------------------------------------------
// Device scratch (allocation-free rule: __device__ globals)
// ---------------------------------------------------------------------------
__device__ float g_values[T_HORIZON];
__device__ float g_lp[T_HORIZON];
__device__ float g_adv[T_HORIZON];
__device__ float g_vlast;
__device__ float g_sums[3];   // sum(adv), sum(adv^2), sum(huber(adv))

// ---------------------------------------------------------------------------
// K1: fused value-net + policy-net forward for a 128-row tile.
// Produces g_values[row] and g_lp[row] (Gaussian log-prob of a given mu).
// ---------------------------------------------------------------------------
__global__ __launch_bounds__(256, 1)
void mlp_kernel(const float* __restrict__ s, const float* __restrict__ a,
                const float* __restrict__ piW1, const float* __restrict__ pib1,
                const float* __restrict__ piW2, const float* __restrict__ pib2,
                const float* __restrict__ muW,  const float* __restrict__ mub,
                const float* __restrict__ logstd,
                const float* __restrict__ vW1,  const float* __restrict__ vb1,
                const float* __restrict__ vW2,  const float* __restrict__ vb2,
                const float* __restrict__ vhW,  const float* __restrict__ vhb)
{
    extern __shared__ float sm[];
    float* X    = sm;                       // [128][XPAD]  s tile
    float* H    = X + TM * XPAD;            // [128][HPAD]  hidden
    float* Wt   = H + TM * HPAD;            // [KT][128]    weight K-slice
    float* Vals = Wt + KT * 128;            // [128]
    float* Mu   = Vals + TM;                // [128][8]

    const int tid = threadIdx.x;
    const int tx  = tid & 15;               // 16 col-groups (8 cols each)
    const int ty  = tid >> 4;               // 16 row-groups (8 rows each)
    const int row0 = blockIdx.x * TM;

    // load s tile (coalesced float4)
    for (int v = tid; v < TM * 32; v += 256) {
        int r = v >> 5, c4 = v & 31;
        float4 val = ((const float4*)(s + (long)(row0 + r) * S_DIM))[c4];
        *(float4*)&X[r * XPAD + c4 * 4] = val;
    }
    if (tid < TM) Vals[tid] = 0.f;
    for (int v = tid; v < TM * A_DIM; v += 256) Mu[v] = 0.f;
    __syncthreads();

    for (int net = 0; net < 2; ++net) {
        const float* W1 = net ? piW1 : vW1;
        const float* b1 = net ? pib1 : vb1;
        const float* W2 = net ? piW2 : vW2;
        const float* b2 = net ? pib2 : vb2;

        // ------------- Layer 1: H = tanh(X @ W1 + b1)  (K = 128) -----------
        for (int nh = 0; nh < 2; ++nh) {
            float acc[8][8];
            #pragma unroll
            for (int i = 0; i < 8; ++i)
                #pragma unroll
                for (int j = 0; j < 8; ++j) acc[i][j] = 0.f;

            for (int k0 = 0; k0 < S_DIM; k0 += KT) {
                __syncthreads();
                for (int v = tid; v < KT * 32; v += 256) {
                    int kk = v >> 5, c4 = v & 31;
                    *(float4*)&Wt[kk * 128 + c4 * 4] =
                        *(const float4*)&W1[(long)(k0 + kk) * HID + nh * 128 + c4 * 4];
                }
                __syncthreads();
                #pragma unroll
                for (int kk = 0; kk < KT; ++kk) {
                    float av[8], bv[8];
                    #pragma unroll
                    for (int i = 0; i < 8; ++i) av[i] = X[(ty * 8 + i) * XPAD + k0 + kk];
                    #pragma unroll
                    for (int j = 0; j < 8; ++j) bv[j] = Wt[kk * 128 + tx * 8 + j];
                    #pragma unroll
                    for (int i = 0; i < 8; ++i)
                        #pragma unroll
                        for (int j = 0; j < 8; ++j) acc[i][j] = fmaf(av[i], bv[j], acc[i][j]);
                }
            }
            __syncthreads();
            #pragma unroll
            for (int i = 0; i < 8; ++i)
                #pragma unroll
                for (int j = 0; j < 8; ++j) {
                    int c = nh * 128 + tx * 8 + j;
                    H[(ty * 8 + i) * HPAD + c] = tanhf(acc[i][j] + b1[c]);
                }
        }
        __syncthreads();

        // ------------- Layer 2 + fused head  (K = 256) ---------------------
        for (int nh = 0; nh < 2; ++nh) {
            float acc[8][8];
            #pragma unroll
            for (int i = 0; i < 8; ++i)
                #pragma unroll
                for (int j = 0; j < 8; ++j) acc[i][j] = 0.f;

            for (int k0 = 0; k0 < HID; k0 += KT) {
                __syncthreads();
                for (int v = tid; v < KT * 32; v += 256) {
                    int kk = v >> 5, c4 = v & 31;
                    *(float4*)&Wt[kk * 128 + c4 * 4] =
                        *(const float4*)&W2[(long)(k0 + kk) * HID + nh * 128 + c4 * 4];
                }
                __syncthreads();
                #pragma unroll
                for (int kk = 0; kk < KT; ++kk) {
                    float av[8], bv[8];
                    #pragma unroll
                    for (int i = 0; i < 8; ++i) av[i] = H[(ty * 8 + i) * HPAD + k0 + kk];
                    #pragma unroll
                    for (int j = 0; j < 8; ++j) bv[j] = Wt[kk * 128 + tx * 8 + j];
                    #pragma unroll
                    for (int i = 0; i < 8; ++i)
                        #pragma unroll
                        for (int j = 0; j < 8; ++j) acc[i][j] = fmaf(av[i], bv[j], acc[i][j]);
                }
            }
            // epilogue: tanh then contract with the head weights, reduce over tx.
            if (net == 0) {
                #pragma unroll
                for (int i = 0; i < 8; ++i) {
                    float rs = 0.f;
                    #pragma unroll
                    for (int j = 0; j < 8; ++j) {
                        int c = nh * 128 + tx * 8 + j;
                        rs += tanhf(acc[i][j] + b2[c]) * vhW[c];
                    }
                    #pragma unroll
                    for (int off = 8; off >= 1; off >>= 1)
                        rs += __shfl_down_sync(0xffffffffu, rs, off, 16);
                    if (tx == 0) Vals[ty * 8 + i] += rs;
                }
            } else {
                #pragma unroll
                for (int i = 0; i < 8; ++i) {
                    float mup[8];
                    #pragma unroll
                    for (int j2 = 0; j2 < 8; ++j2) mup[j2] = 0.f;
                    #pragma unroll
                    for (int j = 0; j < 8; ++j) {
                        int c = nh * 128 + tx * 8 + j;
                        float h2 = tanhf(acc[i][j] + b2[c]);
                        #pragma unroll
                        for (int j2 = 0; j2 < 8; ++j2)
                            mup[j2] = fmaf(h2, muW[c * A_DIM + j2], mup[j2]);
                    }
                    #pragma unroll
                    for (int j2 = 0; j2 < 8; ++j2) {
                        float v = mup[j2];
                        #pragma unroll
                        for (int off = 8; off >= 1; off >>= 1)
                            v += __shfl_down_sync(0xffffffffu, v, off, 16);
                        if (tx == 0) Mu[(ty * 8 + i) * A_DIM + j2] += v;
                    }
                }
            }
        }
        __syncthreads();
    }

    // ------------- per-row finalize: values and log-prob -------------------
    if (tid < TM) {
        int gr = row0 + tid;
        g_values[gr] = Vals[tid] + vhb[0];
        float lp = 0.f;
        #pragma unroll
        for (int j = 0; j < A_DIM; ++j) {
            float mu = Mu[tid * A_DIM + j] + mub[j];
            float ls = logstd[j];
            float z = (a[(long)gr * A_DIM + j] - mu) / expf(ls);
            lp += -0.5f * z * z - ls;
        }
        lp -= 0.5f * LOG2PI_F * (float)A_DIM;
        g_lp[gr] = lp;
    }
}

// ---------------------------------------------------------------------------
// K0: v(sp[-1])  (one GEMV chain, 256 threads)
// ---------------------------------------------------------------------------
__global__ __launch_bounds__(256)
void vlast_kernel(const float* __restrict__ sp,
                  const float* __restrict__ vW1, const float* __restrict__ vb1,
                  const float* __restrict__ vW2, const float* __restrict__ vb2,
                  const float* __restrict__ vhW, const float* __restrict__ vhb)
{
    __shared__ float srow[S_DIM];
    __shared__ float h1[HID];
    __shared__ float red[HID];
    int tid = threadIdx.x;
    if (tid < S_DIM) srow[tid] = sp[(long)(T_HORIZON - 1) * S_DIM + tid];
    __syncthreads();

    float acc = vb1[tid];
    #pragma unroll 4
    for (int k = 0; k < S_DIM; ++k) acc = fmaf(srow[k], vW1[(long)k * HID + tid], acc);
    h1[tid] = tanhf(acc);
    __syncthreads();

    float acc2 = vb2[tid];
    #pragma unroll 4
    for (int k = 0; k < HID; ++k) acc2 = fmaf(h1[k], vW2[(long)k * HID + tid], acc2);
    red[tid] = tanhf(acc2) * vhW[tid];
    __syncthreads();

    for (int off = 128; off >= 1; off >>= 1) {
        if (tid < off) red[tid] += red[tid + off];
        __syncthreads();
    }
    if (tid == 0) g_vlast = red[0] + vhb[0];
}

// ---------------------------------------------------------------------------
// K2: GAE as a parallel suffix scan of affine maps g -> B + A*g.
// Also reduces sum(adv), sum(adv^2), sum(huber(adv))  [vf_loss shortcut:
// v(s) - returns == -adv_unnorm, huber is symmetric].
// ---------------------------------------------------------------------------
__global__ __launch_bounds__(1024)
void gae_kernel(const float* __restrict__ r, const float* __restrict__ dmask)
{
    __shared__ float sA[1024], sB[1024], sC[1024];
    const int t = threadIdx.x;
    const int SEG = T_HORIZON / 1024;    // 64
    const int lo = t * SEG, hi = lo + SEG - 1;
    const float vlast = g_vlast;
    const float gl = GAMMA * LMBDA;

    // local affine composition (processed in descending index order)
    float A = 1.f, B = 0.f;
    for (int i = hi; i >= lo; --i) {
        float nv = (i == T_HORIZON - 1) ? vlast : g_values[i + 1];
        float m = dmask[i];
        float delta = r[i] + GAMMA * nv * m - g_values[i];
        float c = gl * m;
        B = delta + c * B;
        A = c * A;
    }
    sA[t] = A; sB[t] = B;
    __syncthreads();

    // Hillis-Steele inclusive suffix scan over affine maps
    for (int d = 1; d < 1024; d <<= 1) {
        float as = sA[t], bs = sB[t];
        float a2 = 1.f, b2 = 0.f;
        if (t + d < 1024) { a2 = sA[t + d]; b2 = sB[t + d]; }
        __syncthreads();
        sA[t] = as * a2;
        sB[t] = bs + as * b2;
        __syncthreads();
    }
    float g = (t < 1023) ? sB[t + 1] : 0.f;
    __syncthreads();

    // replay segment with true incoming carry, write adv + reduce
    float s1 = 0.f, s2 = 0.f, sh = 0.f;
    for (int i = hi; i >= lo; --i) {
        float nv = (i == T_HORIZON - 1) ? vlast : g_values[i + 1];
        float m = dmask[i];
        float delta = r[i] + GAMMA * nv * m - g_values[i];
        g = delta + gl * m * g;
        g_adv[i] = g;
        s1 += g;
        s2 = fmaf(g, g, s2);
        float ag = fabsf(g);
        sh += (ag < 1.f) ? 0.5f * g * g : ag - 0.5f;
    }
    sA[t] = s1; sB[t] = s2; sC[t] = sh;
    __syncthreads();
    for (int off = 512; off >= 1; off >>= 1) {
        if (t < off) { sA[t] += sA[t + off]; sB[t] += sB[t + off]; sC[t] += sC[t + off]; }
        __syncthreads();
    }
    if (t == 0) { g_sums[0] = sA[0]; g_sums[1] = sB[0]; g_sums[2] = sC[0]; }
}

// ---------------------------------------------------------------------------
// K3: PPO clipped objective + final scalar (single block, deterministic)
// ---------------------------------------------------------------------------
__global__ __launch_bounds__(1024)
void loss_kernel(const float* __restrict__ lpold, const float* __restrict__ logstd,
                 float* __restrict__ out)
{
    __shared__ float red[1024];
    const int t = threadIdx.x;
    const float Tf = (float)T_HORIZON;
    const float sum = g_sums[0], sum2 = g_sums[1], hub = g_sums[2];
    const float mean = sum / Tf;
    const float var = (sum2 - sum * sum / Tf) / (Tf - 1.f);
    const float sd = sqrtf(fmaxf(var, 0.f)) + 1e-8f;

    float acc = 0.f;
    for (int i = t; i < T_HORIZON; i += 1024) {
        float ratio = expf(g_lp[i] - lpold[i]);
        float adv = (g_adv[i] - mean) / sd;
        float rc = fminf(fmaxf(ratio, 1.f - EPS_CLIP), 1.f + EPS_CLIP);
        acc += fminf(ratio * adv, rc * adv);
    }
    red[t] = acc;
    __syncthreads();
    for (int off = 512; off >= 1; off >>= 1) {
        if (t < off) red[t] += red[t + off];
        __syncthreads();
    }
    if (t == 0) {
        float pg = -red[0] / Tf;
        float vf = hub / Tf;
        float ent = 0.f;
        #pragma unroll
        for (int j = 0; j < A_DIM; ++j) ent += 0.5f + 0.5f * LOG2PI_F + logstd[j];
        ent /= (float)A_DIM;
        out[0] = pg + VF_COEF * vf - ENT_COEF * ent;
    }
}

// ---------------------------------------------------------------------------
// Launch
// ---------------------------------------------------------------------------
extern "C" void kernel_launch(void* const* d_in, const int* in_sizes, int n_in,
                              void* d_out, int out_size)
{
    const float* s      = (const float*)d_in[0];
    const float* a      = (const float*)d_in[1];
    const float* r      = (const float*)d_in[2];
    const float* sp     = (const float*)d_in[3];
    const float* lpold  = (const float*)d_in[4];
    const float* dmask  = (const float*)d_in[5];
    const float* piW1   = (const float*)d_in[6];
    const float* pib1   = (const float*)d_in[7];
    const float* piW2   = (const float*)d_in[8];
    const float* pib2   = (const float*)d_in[9];
    const float* muW    = (const float*)d_in[10];
    const float* mub    = (const float*)d_in[11];
    const float* logstd = (const float*)d_in[12];
    const float* vW1    = (const float*)d_in[13];
    const float* vb1    = (const float*)d_in[14];
    const float* vW2    = (const float*)d_in[15];
    const float* vb2    = (const float*)d_in[16];
    const float* vhW    = (const float*)d_in[17];
    const float* vhb    = (const float*)d_in[18];
    float* out = (float*)d_out;

    const int smem_bytes = (TM * XPAD + TM * HPAD + KT * 128 + TM + TM * A_DIM) * 4;
    cudaFuncSetAttribute(mlp_kernel, cudaFuncAttributeMaxDynamicSharedMemorySize, smem_bytes);

    mlp_kernel<<<T_HORIZON / TM, 256, smem_bytes>>>(
        s, a, piW1, pib1, piW2, pib2, muW, mub, logstd,
        vW1, vb1, vW2, vb2, vhW, vhb);
    vlast_kernel<<<1, 256>>>(sp, vW1, vb1, vW2, vb2, vhW, vhb);
    gae_kernel<<<1, 1024>>>(r, dmask);
    loss_kernel<<<1, 1024>>>(lpold, logstd, out);
}

// round 4
// speedup vs baseline: 3.0348x; 3.0348x over previous
#include <cuda_runtime.h>
#include <cuda_bf16.h>
#include <math.h>
#include <stdint.h>

// ---------------------------------------------------------------------------
#define T_HORIZON 65536
#define S_DIM     128
#define A_DIM     8
#define HID       256
#define GAMMA     0.99f
#define LMBDA     0.95f
#define EPS_CLIP  0.2f
#define VF_COEF   0.5f
#define ENT_COEF  0.01f
#define LOG2PI_F  1.8378770664093453f

#define TM 128

// SMEM layout (byte offsets into dynamic smem)
//  X/H union region at 0:
//   X: [128 rows][136 elem pad] bf16  hi @0 (34816B), lo @34816
//   H: [128 rows][264 elem pad] bf16  hi @0 (67584B), lo @67584
#define XSTR      272            // X row stride bytes (136 bf16)
#define HSTR      528            // H row stride bytes (264 bf16)
#define X_LO_OFF  34816
#define H_LO_OFF  67584
#define W_OFF     135168         // W slice: [256 n][72 elem pad] bf16
#define W_LO_OFF  (W_OFF + 36864)
#define SM_B1     208896
#define SM_B2     209920
#define SM_VH     210944
#define SM_MUW    211968
#define SMEM_TOT  220160
// epilogue scratch aliases W region:
#define VP_OFF    W_OFF          // float [4][128]
#define MP_OFF    (W_OFF + 2048) // float [4][128][8]

// ---------------------------------------------------------------------------
// Device scratch
// ---------------------------------------------------------------------------
__device__ float g_values[T_HORIZON];
__device__ float g_lp[T_HORIZON];
__device__ float g_adv[T_HORIZON];
__device__ float g_scanA[T_HORIZON];
__device__ float g_scanB[T_HORIZON];
__device__ float g_vlast;
__device__ float g_blkA[64], g_blkB[64], g_carry[64];
__device__ float g_part[64][3];
__device__ float g_pg[64];
__device__ __nv_bfloat16 g_W1T_hi[2][HID * S_DIM];   // [net][n*128+k]
__device__ __nv_bfloat16 g_W1T_lo[2][HID * S_DIM];
__device__ __nv_bfloat16 g_W2T_hi[2][HID * HID];     // [net][n*256+k]
__device__ __nv_bfloat16 g_W2T_lo[2][HID * HID];

// ---------------------------------------------------------------------------
// Helpers
// ---------------------------------------------------------------------------
__device__ __forceinline__ void mma4(float c[4], const uint32_t a[4], const uint32_t b[2]) {
    asm volatile("mma.sync.aligned.m16n8k16.row.col.f32.bf16.bf16.f32 "
        "{%0,%1,%2,%3}, {%4,%5,%6,%7}, {%8,%9}, {%0,%1,%2,%3};"
        : "+f"(c[0]), "+f"(c[1]), "+f"(c[2]), "+f"(c[3])
        : "r"(a[0]), "r"(a[1]), "r"(a[2]), "r"(a[3]), "r"(b[0]), "r"(b[1]));
}

__device__ __forceinline__ void split2(float x, float y, uint32_t& hi, uint32_t& lo) {
    __nv_bfloat16 xh = __float2bfloat16(x);
    __nv_bfloat16 xl = __float2bfloat16(x - __bfloat162float(xh));
    __nv_bfloat16 yh = __float2bfloat16(y);
    __nv_bfloat16 yl = __float2bfloat16(y - __bfloat162float(yh));
    hi = ((uint32_t)__bfloat16_as_ushort(yh) << 16) | __bfloat16_as_ushort(xh);
    lo = ((uint32_t)__bfloat16_as_ushort(yl) << 16) | __bfloat16_as_ushort(xl);
}

// One K=16 step: A from X/H region (hi @0, lo @a_lo_off), B from W region.
__device__ __forceinline__ void do_kstep(char* sm8, int a_lo_off, int astr,
                                         int kglob, int klocal,
                                         int wm, int wn, int gid, int tig,
                                         float (&acc)[2][8][4])
{
    uint32_t Ah[2][4], Al[2][4];
    #pragma unroll
    for (int mi = 0; mi < 2; ++mi) {
        int row = wm * 32 + mi * 16 + gid;
        const char* p = sm8 + row * astr + kglob * 2 + tig * 4;
        Ah[mi][0] = *(const uint32_t*)(p);
        Ah[mi][1] = *(const uint32_t*)(p + 8 * astr);
        Ah[mi][2] = *(const uint32_t*)(p + 16);
        Ah[mi][3] = *(const uint32_t*)(p + 8 * astr + 16);
        const char* q = p + a_lo_off;
        Al[mi][0] = *(const uint32_t*)(q);
        Al[mi][1] = *(const uint32_t*)(q + 8 * astr);
        Al[mi][2] = *(const uint32_t*)(q + 16);
        Al[mi][3] = *(const uint32_t*)(q + 8 * astr + 16);
    }
    uint32_t B[8][2];
    #pragma unroll
    for (int ni = 0; ni < 8; ++ni) {
        int n = wn * 64 + ni * 8 + gid;
        const char* p = sm8 + W_OFF + n * 144 + klocal * 2 + tig * 4;
        B[ni][0] = *(const uint32_t*)(p);
        B[ni][1] = *(const uint32_t*)(p + 16);
    }
    #pragma unroll
    for (int mi = 0; mi < 2; ++mi)
        #pragma unroll
        for (int ni = 0; ni < 8; ++ni) {
            mma4(acc[mi][ni], Ah[mi], B[ni]);
            mma4(acc[mi][ni], Al[mi], B[ni]);
        }
    #pragma unroll
    for (int ni = 0; ni < 8; ++ni) {
        int n = wn * 64 + ni * 8 + gid;
        const char* p = sm8 + W_LO_OFF + n * 144 + klocal * 2 + tig * 4;
        B[ni][0] = *(const uint32_t*)(p);
        B[ni][1] = *(const uint32_t*)(p + 16);
    }
    #pragma unroll
    for (int mi = 0; mi < 2; ++mi)
        #pragma unroll
        for (int ni = 0; ni < 8; ++ni)
            mma4(acc[mi][ni], Ah[mi], B[ni]);
}

// ---------------------------------------------------------------------------
// Prep: transpose + split weights to bf16 hi/lo ([n][k], k contiguous)
// ---------------------------------------------------------------------------
__global__ void prep_kernel(const float* __restrict__ vW1, const float* __restrict__ piW1,
                            const float* __restrict__ vW2, const float* __restrict__ piW2)
{
    int i = blockIdx.x * 256 + threadIdx.x;
    if (i < 2 * S_DIM * HID) {
        int net = i >> 15, e = i & 32767;
        int n = e & 255, k = e >> 8;                 // k < 128
        const float* W = net ? piW1 : vW1;
        float w = W[k * HID + n];
        __nv_bfloat16 h = __float2bfloat16(w);
        __nv_bfloat16 l = __float2bfloat16(w - __bfloat162float(h));
        g_W1T_hi[net][n * S_DIM + k] = h;
        g_W1T_lo[net][n * S_DIM + k] = l;
    } else {
        int j = i - 2 * S_DIM * HID;
        int net = j >> 16, e = j & 65535;
        int n = e & 255, k = e >> 8;                 // k < 256
        const float* W = net ? piW2 : vW2;
        float w = W[k * HID + n];
        __nv_bfloat16 h = __float2bfloat16(w);
        __nv_bfloat16 l = __float2bfloat16(w - __bfloat162float(h));
        g_W2T_hi[net][n * HID + k] = h;
        g_W2T_lo[net][n * HID + k] = l;
    }
}

// ---------------------------------------------------------------------------
// Fused value+policy forward, split-bf16 warp MMA
// ---------------------------------------------------------------------------
__global__ __launch_bounds__(512, 1)
void mlp_kernel(const float* __restrict__ s, const float* __restrict__ a,
                const float* __restrict__ vb1, const float* __restrict__ vb2,
                const float* __restrict__ pib1, const float* __restrict__ pib2,
                const float* __restrict__ vhW, const float* __restrict__ vhb,
                const float* __restrict__ muW, const float* __restrict__ mub,
                const float* __restrict__ logstd)
{
    extern __shared__ char sm8[];
    float* smf = (float*)sm8;
    const int tid = threadIdx.x;
    const int w = tid >> 5, lane = tid & 31;
    const int wm = w & 3, wn = w >> 2;           // warp tile: rows wm*32.., cols wn*64..
    const int gid = lane >> 2, tig = lane & 3;
    const int row0 = blockIdx.x * TM;

    for (int net = 0; net < 2; ++net) {
        const __nv_bfloat16* W1h = g_W1T_hi[net];
        const __nv_bfloat16* W1l = g_W1T_lo[net];
        const __nv_bfloat16* W2h = g_W2T_hi[net];
        const __nv_bfloat16* W2l = g_W2T_lo[net];
        const float* b1 = net ? pib1 : vb1;
        const float* b2 = net ? pib2 : vb2;

        // ---- stage X (s tile -> bf16 hi/lo, padded) + small arrays ----
        for (int idx = tid; idx < TM * 64; idx += 512) {
            int row = idx >> 6, k = (idx & 63) * 2;
            float2 x = *(const float2*)(s + (long)(row0 + row) * S_DIM + k);
            uint32_t hi, lo;
            split2(x.x, x.y, hi, lo);
            *(uint32_t*)(sm8 + row * XSTR + k * 2) = hi;
            *(uint32_t*)(sm8 + X_LO_OFF + row * XSTR + k * 2) = lo;
        }
        if (tid < 256) {
            smf[SM_B1 / 4 + tid] = b1[tid];
            smf[SM_B2 / 4 + tid] = b2[tid];
            if (net == 0) smf[SM_VH / 4 + tid] = vhW[tid];
        }
        if (net == 1)
            for (int idx = tid; idx < 2048; idx += 512) smf[SM_MUW / 4 + idx] = muW[idx];

        float acc[2][8][4];
        #pragma unroll
        for (int mi = 0; mi < 2; ++mi)
            #pragma unroll
            for (int ni = 0; ni < 8; ++ni)
                #pragma unroll
                for (int c = 0; c < 4; ++c) acc[mi][ni][c] = 0.f;

        // ---- GEMM1: C = X @ W1, K=128 in 2 slices of 64 ----
        for (int sl = 0; sl < 2; ++sl) {
            __syncthreads();
            for (int idx = tid; idx < 256 * 32; idx += 512) {
                int n = idx >> 5, k2 = idx & 31;
                int srcu = (n * S_DIM + sl * 64) / 2 + k2;
                *(uint32_t*)(sm8 + W_OFF + n * 144 + k2 * 4) = ((const uint32_t*)W1h)[srcu];
                *(uint32_t*)(sm8 + W_LO_OFF + n * 144 + k2 * 4) = ((const uint32_t*)W1l)[srcu];
            }
            __syncthreads();
            #pragma unroll
            for (int ks = 0; ks < 4; ++ks)
                do_kstep(sm8, X_LO_OFF, XSTR, sl * 64 + ks * 16, ks * 16, wm, wn, gid, tig, acc);
        }
        __syncthreads();

        // ---- epilogue1: H = tanh(C + b1) -> hi/lo bf16 (overwrites X) ----
        #pragma unroll
        for (int mi = 0; mi < 2; ++mi)
            #pragma unroll
            for (int ni = 0; ni < 8; ++ni) {
                int row = wm * 32 + mi * 16 + gid;
                int col = wn * 64 + ni * 8 + tig * 2;
                float bb0 = smf[SM_B1 / 4 + col], bb1 = smf[SM_B1 / 4 + col + 1];
                uint32_t hi, lo;
                split2(tanhf(acc[mi][ni][0] + bb0), tanhf(acc[mi][ni][1] + bb1), hi, lo);
                *(uint32_t*)(sm8 + row * HSTR + col * 2) = hi;
                *(uint32_t*)(sm8 + H_LO_OFF + row * HSTR + col * 2) = lo;
                split2(tanhf(acc[mi][ni][2] + bb0), tanhf(acc[mi][ni][3] + bb1), hi, lo);
                *(uint32_t*)(sm8 + (row + 8) * HSTR + col * 2) = hi;
                *(uint32_t*)(sm8 + H_LO_OFF + (row + 8) * HSTR + col * 2) = lo;
                acc[mi][ni][0] = acc[mi][ni][1] = acc[mi][ni][2] = acc[mi][ni][3] = 0.f;
            }

        // ---- GEMM2: C2 = H @ W2, K=256 in 4 slices of 64 ----
        for (int sl = 0; sl < 4; ++sl) {
            __syncthreads();
            for (int idx = tid; idx < 256 * 32; idx += 512) {
                int n = idx >> 5, k2 = idx & 31;
                int srcu = (n * HID + sl * 64) / 2 + k2;
                *(uint32_t*)(sm8 + W_OFF + n * 144 + k2 * 4) = ((const uint32_t*)W2h)[srcu];
                *(uint32_t*)(sm8 + W_LO_OFF + n * 144 + k2 * 4) = ((const uint32_t*)W2l)[srcu];
            }
            __syncthreads();
            #pragma unroll
            for (int ks = 0; ks < 4; ++ks)
                do_kstep(sm8, H_LO_OFF, HSTR, sl * 64 + ks * 16, ks * 16, wm, wn, gid, tig, acc);
        }
        __syncthreads();   // W region free -> scratch

        // ---- epilogue2: heads ----
        if (net == 0) {
            float vs[4] = {0.f, 0.f, 0.f, 0.f};
            #pragma unroll
            for (int mi = 0; mi < 2; ++mi)
                #pragma unroll
                for (int ni = 0; ni < 8; ++ni) {
                    int col = wn * 64 + ni * 8 + tig * 2;
                    float bb0 = smf[SM_B2 / 4 + col], bb1 = smf[SM_B2 / 4 + col + 1];
                    float v0 = smf[SM_VH / 4 + col], v1 = smf[SM_VH / 4 + col + 1];
                    vs[2 * mi]     += tanhf(acc[mi][ni][0] + bb0) * v0 + tanhf(acc[mi][ni][1] + bb1) * v1;
                    vs[2 * mi + 1] += tanhf(acc[mi][ni][2] + bb0) * v0 + tanhf(acc[mi][ni][3] + bb1) * v1;
                }
            #pragma unroll
            for (int q = 0; q < 4; ++q) {
                float v = vs[q];
                v += __shfl_down_sync(0xffffffffu, v, 2, 4);
                v += __shfl_down_sync(0xffffffffu, v, 1, 4);
                if (tig == 0) {
                    int rl = wm * 32 + (q >> 1) * 16 + gid + (q & 1) * 8;
                    smf[VP_OFF / 4 + wn * 128 + rl] = v;
                }
            }
        } else {
            #pragma unroll
            for (int mi = 0; mi < 2; ++mi) {
                float mus[2][8];
                #pragma unroll
                for (int ss = 0; ss < 2; ++ss)
                    #pragma unroll
                    for (int j = 0; j < 8; ++j) mus[ss][j] = 0.f;
                #pragma unroll
                for (int ni = 0; ni < 8; ++ni) {
                    int col = wn * 64 + ni * 8 + tig * 2;
                    float bb0 = smf[SM_B2 / 4 + col], bb1 = smf[SM_B2 / 4 + col + 1];
                    float h0 = tanhf(acc[mi][ni][0] + bb0), h1 = tanhf(acc[mi][ni][1] + bb1);
                    float h2 = tanhf(acc[mi][ni][2] + bb0), h3 = tanhf(acc[mi][ni][3] + bb1);
                    #pragma unroll
                    for (int j = 0; j < 8; ++j) {
                        float w0 = smf[SM_MUW / 4 + col * 8 + j];
                        float w1 = smf[SM_MUW / 4 + (col + 1) * 8 + j];
                        mus[0][j] += h0 * w0 + h1 * w1;
                        mus[1][j] += h2 * w0 + h3 * w1;
                    }
                }
                #pragma unroll
                for (int ss = 0; ss < 2; ++ss) {
                    #pragma unroll
                    for (int j = 0; j < 8; ++j) {
                        float v = mus[ss][j];
                        v += __shfl_down_sync(0xffffffffu, v, 2, 4);
                        v += __shfl_down_sync(0xffffffffu, v, 1, 4);
                        mus[ss][j] = v;
                    }
                    if (tig == 0) {
                        int rl = wm * 32 + mi * 16 + gid + ss * 8;
                        #pragma unroll
                        for (int j = 0; j < 8; ++j)
                            smf[MP_OFF / 4 + (wn * 128 + rl) * 8 + j] = mus[ss][j];
                    }
                }
            }
        }
        __syncthreads();

        // ---- finalize rows ----
        if (tid < TM) {
            if (net == 0) {
                float v = vhb[0];
                #pragma unroll
                for (int g = 0; g < 4; ++g) v += smf[VP_OFF / 4 + g * 128 + tid];
                g_values[row0 + tid] = v;
            } else {
                int gr = row0 + tid;
                float lpv = 0.f;
                #pragma unroll
                for (int j = 0; j < A_DIM; ++j) {
                    float m = mub[j];
                    #pragma unroll
                    for (int g = 0; g < 4; ++g) m += smf[MP_OFF / 4 + (g * 128 + tid) * 8 + j];
                    float ls = logstd[j];
                    float z = (a[(long)gr * A_DIM + j] - m) / expf(ls);
                    lpv += -0.5f * z * z - ls;
                }
                g_lp[gr] = lpv - 0.5f * LOG2PI_F * (float)A_DIM;
            }
        }
        __syncthreads();
    }
}

// ---------------------------------------------------------------------------
// v(sp[-1])  (exact fp32 GEMV chain)
// ---------------------------------------------------------------------------
__global__ __launch_bounds__(256)
void vlast_kernel(const float* __restrict__ sp,
                  const float* __restrict__ vW1, const float* __restrict__ vb1,
                  const float* __restrict__ vW2, const float* __restrict__ vb2,
                  const float* __restrict__ vhW, const float* __restrict__ vhb)
{
    __shared__ float srow[S_DIM], h1[HID], red[HID];
    int tid = threadIdx.x;
    if (tid < S_DIM) srow[tid] = sp[(long)(T_HORIZON - 1) * S_DIM + tid];
    __syncthreads();
    float acc = vb1[tid];
    #pragma unroll 4
    for (int k = 0; k < S_DIM; ++k) acc = fmaf(srow[k], vW1[(long)k * HID + tid], acc);
    h1[tid] = tanhf(acc);
    __syncthreads();
    float acc2 = vb2[tid];
    #pragma unroll 4
    for (int k = 0; k < HID; ++k) acc2 = fmaf(h1[k], vW2[(long)k * HID + tid], acc2);
    red[tid] = tanhf(acc2) * vhW[tid];
    __syncthreads();
    for (int off = 128; off >= 1; off >>= 1) {
        if (tid < off) red[tid] += red[tid + off];
        __syncthreads();
    }
    if (tid == 0) g_vlast = red[0] + vhb[0];
}

// ---------------------------------------------------------------------------
// GAE stage A: per-block suffix scan of affine maps
// ---------------------------------------------------------------------------
__global__ __launch_bounds__(1024)
void gae_scan_kernel(const float* __restrict__ r, const float* __restrict__ dmask)
{
    __shared__ float sA[1024], sB[1024];
    const int t = threadIdx.x, b = blockIdx.x;
    const int i = b * 1024 + t;
    float nv = (i == T_HORIZON - 1) ? g_vlast : g_values[i + 1];
    float m = dmask[i];
    float A = GAMMA * LMBDA * m;
    float B = r[i] + GAMMA * nv * m - g_values[i];
    sA[t] = A; sB[t] = B;
    __syncthreads();
    for (int d = 1; d < 1024; d <<= 1) {
        float as = sA[t], bs = sB[t];
        float a2 = 1.f, b2 = 0.f;
        if (t + d < 1024) { a2 = sA[t + d]; b2 = sB[t + d]; }
        __syncthreads();
        sA[t] = as * a2;
        sB[t] = bs + as * b2;
        __syncthreads();
    }
    g_scanA[i] = sA[t]; g_scanB[i] = sB[t];
    if (t == 0) { g_blkA[b] = sA[0]; g_blkB[b] = sB[0]; }
}

// GAE stage B: serial carry across 64 blocks (deterministic)
__global__ void gae_carry_kernel()
{
    if (threadIdx.x == 0) {
        float g = 0.f;
        for (int b = 63; b >= 0; --b) {
            g_carry[b] = g;
            g = g_blkB[b] + g_blkA[b] * g;
        }
    }
}

// GAE stage C: finalize adv + partial sums (sum, sum2, huber)
__global__ __launch_bounds__(1024)
void gae_final_kernel()
{
    __shared__ float sA[1024], sB[1024], sC[1024];
    const int t = threadIdx.x, b = blockIdx.x;
    const int i = b * 1024 + t;
    float g = g_scanB[i] + g_scanA[i] * g_carry[b];
    g_adv[i] = g;
    float ag = fabsf(g);
    sA[t] = g; sB[t] = g * g; sC[t] = (ag < 1.f) ? 0.5f * g * g : ag - 0.5f;
    __syncthreads();
    for (int off = 512; off >= 1; off >>= 1) {
        if (t < off) { sA[t] += sA[t + off]; sB[t] += sB[t + off]; sC[t] += sC[t + off]; }
        __syncthreads();
    }
    if (t == 0) { g_part[b][0] = sA[0]; g_part[b][1] = sB[0]; g_part[b][2] = sC[0]; }
}

// Loss partials
__global__ __launch_bounds__(1024)
void loss_part_kernel(const float* __restrict__ lpold)
{
    __shared__ float red[1024];
    __shared__ float s_mean, s_sd;
    const int t = threadIdx.x, b = blockIdx.x;
    if (t == 0) {
        float s1 = 0.f, s2 = 0.f;
        for (int k = 0; k < 64; ++k) { s1 += g_part[k][0]; s2 += g_part[k][1]; }
        const float Tf = (float)T_HORIZON;
        s_mean = s1 / Tf;
        float var = (s2 - s1 * s1 / Tf) / (Tf - 1.f);
        s_sd = sqrtf(fmaxf(var, 0.f)) + 1e-8f;
    }
    __syncthreads();
    const int i = b * 1024 + t;
    float ratio = expf(g_lp[i] - lpold[i]);
    float adv = (g_adv[i] - s_mean) / s_sd;
    float rc = fminf(fmaxf(ratio, 1.f - EPS_CLIP), 1.f + EPS_CLIP);
    red[t] = fminf(ratio * adv, rc * adv);
    __syncthreads();
    for (int off = 512; off >= 1; off >>= 1) {
        if (t < off) red[t] += red[t + off];
        __syncthreads();
    }
    if (t == 0) g_pg[b] = red[0];
}

// Final scalar
__global__ void loss_final_kernel(const float* __restrict__ logstd, float* __restrict__ out)
{
    if (threadIdx.x == 0) {
        const float Tf = (float)T_HORIZON;
        float pgs = 0.f, hub = 0.f;
        for (int b = 0; b < 64; ++b) { pgs += g_pg[b]; hub += g_part[b][2]; }
        float ent = 0.f;
        #pragma unroll
        for (int j = 0; j < A_DIM; ++j) ent += 0.5f + 0.5f * LOG2PI_F + logstd[j];
        ent /= (float)A_DIM;
        out[0] = -pgs / Tf + VF_COEF * (hub / Tf) - ENT_COEF * ent;
    }
}

// ---------------------------------------------------------------------------
extern "C" void kernel_launch(void* const* d_in, const int* in_sizes, int n_in,
                              void* d_out, int out_size)
{
    const float* s      = (const float*)d_in[0];
    const float* a      = (const float*)d_in[1];
    const float* r      = (const float*)d_in[2];
    const float* sp     = (const float*)d_in[3];
    const float* lpold  = (const float*)d_in[4];
    const float* dmask  = (const float*)d_in[5];
    const float* piW1   = (const float*)d_in[6];
    const float* pib1   = (const float*)d_in[7];
    const float* piW2   = (const float*)d_in[8];
    const float* pib2   = (const float*)d_in[9];
    const float* muW    = (const float*)d_in[10];
    const float* mub    = (const float*)d_in[11];
    const float* logstd = (const float*)d_in[12];
    const float* vW1    = (const float*)d_in[13];
    const float* vb1    = (const float*)d_in[14];
    const float* vW2    = (const float*)d_in[15];
    const float* vb2    = (const float*)d_in[16];
    const float* vhW    = (const float*)d_in[17];
    const float* vhb    = (const float*)d_in[18];
    float* out = (float*)d_out;

    cudaFuncSetAttribute(mlp_kernel, cudaFuncAttributeMaxDynamicSharedMemorySize, SMEM_TOT);

    prep_kernel<<<768, 256>>>(vW1, piW1, vW2, piW2);
    mlp_kernel<<<T_HORIZON / TM, 512, SMEM_TOT>>>(s, a, vb1, vb2, pib1, pib2,
                                                  vhW, vhb, muW, mub, logstd);
    vlast_kernel<<<1, 256>>>(sp, vW1, vb1, vW2, vb2, vhW, vhb);
    gae_scan_kernel<<<64, 1024>>>(r, dmask);
    gae_carry_kernel<<<1, 32>>>();
    gae_final_kernel<<<64, 1024>>>();
    loss_part_kernel<<<64, 1024>>>(lpold);
    loss_final_kernel<<<1, 32>>>(logstd, out);
}